// round 8
// baseline (speedup 1.0000x reference)
#include <cuda_runtime.h>
#include <cuda_bf16.h>
#include <math.h>

// ---------------------------------------------------------------------------
// SpectralAnalyzer: rfft2 -> mag/phase -> radial/azimuthal stats ->
// bilinear resize -> 2x (conv3x3+bn+relu) branches (pooled) ->
// conv1d branch -> MLP head with LayerNorm.
// Shapes: x [16,3,256,256] -> out [16,128] fp32.
//
// Numerical-matching rules (vs the jax/XLA GPU reference):
//  * XLA's algebraic simplifier rewrites divide-by-constant into
//    multiply-by-reciprocal. We emulate that on every bin-index chain
//    (radius/denom, (ang+pi)/2pi, angle/pi, and constant-count divides).
//  * transcendentals (atan2f/hypotf/log1pf) lower to the same libdevice
//    functions XLA emits and are NOT affected by --use_fast_math
//  * every add/mul/sub/sqrt on a BIN-INDEX path uses forced round-to-nearest
//    intrinsics so fast-math cannot substitute approximate ops
//  * contractions are plain fp32 (TF32 emulation tested: worsened error)
// ---------------------------------------------------------------------------

#define B_     16
#define C_     3
#define H_     256
#define W_     256
#define WF     129            // W/2+1
#define NPTS   (H_ * WF)      // 33024
#define NRAD   32
#define NAZ    8
#define PI_F   3.14159265358979323846f
#define TWOPI_F 6.28318530717958647692f

// ------------------------- scratch (device globals) ------------------------
__device__ float2 g_tw   [128];                        // e^{-2*pi*i*k/256}
__device__ float2 g_freq [B_ * C_ * H_ * WF];          // row-fft intermediate
__device__ float  g_mag  [B_ * C_ * H_ * WF];
__device__ float  g_phase[B_ * C_ * H_ * WF];
__device__ float  g_magsp[B_ * C_ * H_ * W_];
__device__ float  g_phsp [B_ * C_ * H_ * W_];
__device__ float  g_featm[(size_t)B_ * 64 * H_ * W_];  // 268 MB
__device__ float  g_featp[(size_t)B_ * 32 * H_ * W_];  // 134 MB
__device__ float  g_radial[B_ * C_ * NRAD];
__device__ float  g_az    [B_ * NAZ * 2 * C_];
__device__ float  g_poolm [B_ * 64];
__device__ float  g_poolp [B_ * 32];

__device__ __forceinline__ float n2n(float v) {
    if (isnan(v)) return 0.f;
    if (isinf(v)) return v > 0.f ? 1e4f : -1e4f;
    return v;
}

// --------------------- twiddle table (double-accurate) ---------------------
__global__ void init_tw_kernel() {
    int k = threadIdx.x;                       // 128 threads
    double ang = -6.283185307179586476925286766559 * (double)k / 256.0;
    double s, c;
    sincos(ang, &s, &c);
    g_tw[k] = make_float2((float)c, (float)s);
    // zero pooled sums too (fused housekeeping)
    if (k < 64) {
        #pragma unroll
        for (int b = 0; b < B_; ++b) g_poolm[b * 64 + k] = 0.f;
    }
    if (k < 32) {
        #pragma unroll
        for (int b = 0; b < B_; ++b) g_poolp[b * 32 + k] = 0.f;
    }
}

// ------------------------------ FFT (len 256) ------------------------------
// In-place radix-2 DIT on shared arrays; caller loads with bit-reversed index.
// blockDim.x == 128 (one butterfly per thread per stage). stw = 128 twiddles.
__device__ __forceinline__ void fft256(float* re, float* im,
                                       const float2* stw, int t) {
    #pragma unroll
    for (int len = 2; len <= 256; len <<= 1) {
        int half = len >> 1;
        int grp  = t / half;
        int pos  = t - grp * half;
        int i0   = grp * len + pos;
        int i1   = i0 + half;
        float2 w = stw[pos * (256 / len)];
        float ar = re[i0], ai = im[i0];
        float br = re[i1], bi = im[i1];
        float tr = w.x * br - w.y * bi;
        float ti = w.x * bi + w.y * br;
        re[i0] = ar + tr;  im[i0] = ai + ti;
        re[i1] = ar - tr;  im[i1] = ai - ti;
        __syncthreads();
    }
}

__global__ void rowfft_kernel(const float* __restrict__ x) {
    int row = blockIdx.x;                       // (b*C+c)*H + h, 12288 total
    const float* px = x + (size_t)row * W_;
    __shared__ float sre[256], sim[256];
    __shared__ float2 stw[128];
    int t = threadIdx.x;
    stw[t] = g_tw[t];
    #pragma unroll
    for (int i = t; i < 256; i += 128) {
        float v = px[i];
        v = fminf(fmaxf(v, -10.f), 10.f);
        int r = (int)(__brev((unsigned)i) >> 24);
        sre[r] = v;  sim[r] = 0.f;
    }
    __syncthreads();
    fft256(sre, sim, stw, t);
    for (int i = t; i < WF; i += 128)
        g_freq[(size_t)row * WF + i] = make_float2(sre[i], sim[i]);
}

__global__ void colfft_kernel() {
    int col = blockIdx.x;                       // bc*WF + w, 6192 total
    int bc = col / WF, w = col - bc * WF;
    const float2* base = g_freq + (size_t)bc * H_ * WF + w;
    __shared__ float sre[256], sim[256];
    __shared__ float2 stw[128];
    int t = threadIdx.x;
    stw[t] = g_tw[t];
    #pragma unroll
    for (int h = t; h < 256; h += 128) {
        float2 v = base[(size_t)h * WF];
        int r = (int)(__brev((unsigned)h) >> 24);
        sre[r] = v.x;  sim[r] = v.y;
    }
    __syncthreads();
    fft256(sre, sim, stw, t);
    const float INVPI = __fdiv_rn(1.f, PI_F);   // XLA: divide->mul-reciprocal
    #pragma unroll
    for (int h = t; h < 256; h += 128) {
        float re_ = sre[h], im_ = sim[h];
        // libdevice hypotf/atan2f == what XLA emits for abs()/angle()
        float m = hypotf(re_, im_);
        m = fminf(fmaxf(m, 1e-8f), 1e6f);
        float ang = atan2f(im_, re_);
        float ph = __fmul_rn(ang, INVPI);
        ph = fminf(fmaxf(ph, -1.f), 1.f);
        size_t idx = (size_t)bc * NPTS + (size_t)h * WF + w;
        g_mag[idx]   = m;
        g_phase[idx] = ph;
    }
}

// -------------------- radial / azimuthal statistics ------------------------
// Bin indices replicate the reference's fp32 arithmetic op-for-op, INCLUDING
// XLA's divide-by-constant -> multiply-by-reciprocal rewrite (this decides
// the radial corner point's bin and the az bin-5/6 cutoff on the j=0 column).
__global__ void stats_kernel() {
    int bc = blockIdx.x;                        // 48 blocks
    int t  = threadIdx.x;                       // 256 threads
    __shared__ float rs[NRAD], rc[NRAD], s1[NAZ], s2[NAZ], ac[NAZ];
    if (t < NRAD) { rs[t] = 0.f; rc[t] = 0.f; }
    if (t < NAZ)  { s1[t] = 0.f; s2[t] = 0.f; ac[t] = 0.f; }
    __syncthreads();

    const float rmax      = __fsqrt_rn(0.5f);            // max radius on grid
    const float denom     = __fadd_rn(rmax, 1e-8f);
    const float inv_denom = __fdiv_rn(1.f, denom);       // folded reciprocal
    const float C8        = __fmul_rn(__fdiv_rn(1.f, TWOPI_F), 8.f); // exact x8
    const float* magp = g_mag + (size_t)bc * NPTS;
    for (int n = t; n < NPTS; n += 256) {
        int i = n / WF;
        int j = n - i * WF;
        float fy = (float)(i < 128 ? i : i - 256) * (1.f / 256.f);  // exact
        float fx = (float)j * (1.f / 256.f);                        // exact
        float r2s = __fadd_rn(__fmul_rn(fx, fx), __fmul_rn(fy, fy)); // exact
        float radius = __fsqrt_rn(r2s);
        float rv = __fmul_rn(__fmul_rn(radius, inv_denom), 31.0f);
        int rb = (int)rv;  rb = min(max(rb, 0), NRAD - 1);

        float fx2 = __fadd_rn(fx, 1e-8f);
        float ang = atan2f(fy, fx2);            // libdevice __nv_atan2f (as XLA)
        float av  = __fmul_rn(__fadd_rn(ang, PI_F), C8);
        int ab = (int)av;  ab = min(max(ab, 0), NAZ - 1);

        float m = magp[n];
        atomicAdd(&rs[rb], m);
        atomicAdd(&rc[rb], 1.f);
        atomicAdd(&s1[ab], m);
        atomicAdd(&s2[ab], __fmul_rn(m, m));
        atomicAdd(&ac[ab], 1.f);
    }
    __syncthreads();

    int b = bc / C_, c = bc - b * C_;
    if (t < NRAD) {
        float cnt = fmaxf(rc[t], 1.f);
        float v = __fmul_rn(rs[t], __fdiv_rn(1.f, cnt));  // recip rewrite
        g_radial[(b * C_ + c) * NRAD + t] = fminf(fmaxf(v, 0.f), 1e6f);
    }
    if (t < NAZ) {
        float cnt = ac[t];
        float mean = 0.f, sd = 0.f;
        if (cnt > 0.f) {
            mean = __fmul_rn(s1[t], __fdiv_rn(1.f, cnt)); // recip rewrite
            float num = __fsub_rn(s2[t], __fmul_rn(cnt, __fmul_rn(mean, mean)));
            float var = __fmul_rn(num, __fdiv_rn(1.f, fmaxf(cnt - 1.f, 1.f)));
            sd = __fsqrt_rn(fmaxf(var, 0.f));
        }
        // empty bins: 0*inf = NaN in reference -> nan_to_num -> 0 (here: 0)
        g_az[b * (NAZ * 2 * C_) + t * (2 * C_) + c]      = n2n(mean);
        g_az[b * (NAZ * 2 * C_) + t * (2 * C_) + C_ + c] = n2n(sd);
    }
}

// ------------------------- bilinear resize 129 -> 256 ----------------------
__global__ void resize_kernel() {
    int idx = blockIdx.x * blockDim.x + threadIdx.x;
    if (idx >= B_ * C_ * H_ * W_) return;
    int xo = idx & 255;
    int y  = (idx >> 8) & 255;
    int bc = idx >> 16;

    float sx = ((float)xo + 0.5f) * (129.f / 256.f) - 0.5f;  // exact dyadic
    float fl = floorf(sx);
    int j0 = (int)fl;
    float f = sx - fl;
    int ja = max(j0, 0);
    int jb = min(j0 + 1, WF - 1);

    size_t rowbase = (size_t)bc * NPTS + (size_t)y * WF;
    float m0 = g_mag[rowbase + ja], m1 = g_mag[rowbase + jb];
    float l0 = fminf(fmaxf(log1pf(m0), -20.f), 20.f);
    float l1 = fminf(fmaxf(log1pf(m1), -20.f), 20.f);
    g_magsp[idx] = (1.f - f) * l0 + f * l1;

    float p0 = g_phase[rowbase + ja], p1 = g_phase[rowbase + jb];
    g_phsp[idx] = (1.f - f) * p0 + f * p1;
}

// --------------------------- conv3x3 + bn + relu ---------------------------
// Tile 32x32 pixels, 256 threads, 2x2 pixels/thread, COPB output channels per
// block. All COPB*CIN*9 weights preloaded to smem once. If outPool != null:
// fuse bn+relu+spatial-sum (no feature write). Plain fp32 math.
template <int CIN, int COPB>
__global__ void __launch_bounds__(256, 2)
conv3x3_kernel(const float* __restrict__ in, const float* __restrict__ wt,
               const float* __restrict__ bias, const float* __restrict__ bn,
               float* __restrict__ outFeat, float* __restrict__ outPool,
               int Cout)
{
    const int groups = Cout / COPB;
    const int b   = blockIdx.z / groups;
    const int g   = blockIdx.z - b * groups;
    const int coB = g * COPB;
    const int x0  = blockIdx.x * 32, y0 = blockIdx.y * 32;
    const int tid = threadIdx.x;
    const int tx  = (tid & 15) * 2, ty = (tid >> 4) * 2;

    __shared__ float s_in[34 * 34];
    __shared__ float s_w[COPB * CIN * 9];       // [c][ci][9]
    __shared__ float s_pool[COPB];

    // preload the whole weight block once
    for (int idx = tid; idx < COPB * CIN * 9; idx += 256) {
        int c  = idx / (CIN * 9);
        int r  = idx - c * (CIN * 9);           // ci*9 + k
        s_w[idx] = wt[(size_t)(coB + c) * CIN * 9 + r];
    }

    float acc[COPB][4];
    #pragma unroll
    for (int c = 0; c < COPB; ++c)
        acc[c][0] = acc[c][1] = acc[c][2] = acc[c][3] = 0.f;

    for (int ci = 0; ci < CIN; ++ci) {
        const float* plane = in + ((size_t)(b * CIN + ci)) * (H_ * W_);
        __syncthreads();                        // protect s_in reuse (and first-iter s_w)
        for (int idx = tid; idx < 34 * 34; idx += 256) {
            int iy = idx / 34, ix = idx - iy * 34;
            int gy = y0 + iy - 1, gx = x0 + ix - 1;
            s_in[idx] = (gy >= 0 && gy < H_ && gx >= 0 && gx < W_)
                        ? plane[gy * W_ + gx] : 0.f;
        }
        __syncthreads();

        float v[16];
        #pragma unroll
        for (int dy = 0; dy < 4; ++dy)
            #pragma unroll
            for (int dx = 0; dx < 4; ++dx)
                v[dy * 4 + dx] = s_in[(ty + dy) * 34 + tx + dx];

        #pragma unroll
        for (int c = 0; c < COPB; ++c) {
            const float* wc = &s_w[(c * CIN + ci) * 9];
            float w0 = wc[0], w1 = wc[1], w2 = wc[2];
            float w3 = wc[3], w4 = wc[4], w5 = wc[5];
            float w6 = wc[6], w7 = wc[7], w8 = wc[8];
            #pragma unroll
            for (int py = 0; py < 2; ++py)
                #pragma unroll
                for (int px = 0; px < 2; ++px) {
                    float r = acc[c][py * 2 + px];
                    r += w0 * v[py * 4 + px]       + w1 * v[py * 4 + px + 1]       + w2 * v[py * 4 + px + 2];
                    r += w3 * v[(py + 1) * 4 + px] + w4 * v[(py + 1) * 4 + px + 1] + w5 * v[(py + 1) * 4 + px + 2];
                    r += w6 * v[(py + 2) * 4 + px] + w7 * v[(py + 2) * 4 + px + 1] + w8 * v[(py + 2) * 4 + px + 2];
                    acc[c][py * 2 + px] = r;
                }
        }
    }
    __syncthreads();

    if (outPool) {
        if (tid < COPB) s_pool[tid] = 0.f;
        __syncthreads();
    }

    #pragma unroll
    for (int c = 0; c < COPB; ++c) {
        int co = coB + c;
        float gg = bn[co], bb = bn[Cout + co];
        float mm = bn[2 * Cout + co], vv = bn[3 * Cout + co];
        float sc = gg / sqrtf(vv + 1e-5f);
        float bi = bias[co];
        float lsum = 0.f;
        #pragma unroll
        for (int p = 0; p < 4; ++p) {
            float yv = (acc[c][p] + bi - mm) * sc + bb;
            yv = fmaxf(yv, 0.f);
            if (outFeat) {
                int py = ty + (p >> 1), px = tx + (p & 1);
                outFeat[(((size_t)(b * Cout + co)) * H_ + (y0 + py)) * W_ + (x0 + px)] = yv;
            } else {
                lsum += yv;
            }
        }
        if (outPool) {
            #pragma unroll
            for (int o = 16; o; o >>= 1)
                lsum += __shfl_down_sync(0xffffffffu, lsum, o);
            if ((tid & 31) == 0) atomicAdd(&s_pool[c], lsum);
        }
    }
    if (outPool) {
        __syncthreads();
        if (tid < COPB) atomicAdd(&outPool[b * Cout + coB + tid], s_pool[tid]);
    }
}

// -------------- conv1d branch + concat + MLP head + LayerNorm --------------
__global__ void final_kernel(const float* __restrict__ rw1, const float* __restrict__ rb1,
                             const float* __restrict__ rbn1, const float* __restrict__ rw2,
                             const float* __restrict__ rb2, const float* __restrict__ rbn2,
                             const float* __restrict__ lw1, const float* __restrict__ lb1,
                             const float* __restrict__ lng, const float* __restrict__ lnb,
                             const float* __restrict__ lw2, const float* __restrict__ lb2,
                             float* __restrict__ out)
{
    int b = blockIdx.x, t = threadIdx.x;
    __shared__ float s_r0[96], s_r1[1024], s_r2[1024];
    __shared__ float s_comb[176], s_h[256], s_red[256];

    if (t < 96) s_r0[t] = g_radial[b * 96 + t];
    __syncthreads();

    // conv1d 3 -> 32, k=3, SAME, + bn + relu
    for (int idx = t; idx < 1024; idx += 256) {
        int co = idx >> 5, i = idx & 31;
        float s = rb1[co];
        #pragma unroll
        for (int ci = 0; ci < 3; ++ci) {
            const float* wp = &rw1[(co * 3 + ci) * 3];
            if (i > 0)  s += wp[0] * s_r0[ci * 32 + i - 1];
            s += wp[1] * s_r0[ci * 32 + i];
            if (i < 31) s += wp[2] * s_r0[ci * 32 + i + 1];
        }
        float gg = rbn1[co], bb = rbn1[32 + co], mm = rbn1[64 + co], vv = rbn1[96 + co];
        s = (s - mm) * (gg / sqrtf(vv + 1e-5f)) + bb;
        s_r1[idx] = fmaxf(s, 0.f);
    }
    __syncthreads();

    // conv1d 32 -> 32
    for (int idx = t; idx < 1024; idx += 256) {
        int co = idx >> 5, i = idx & 31;
        float s = rb2[co];
        for (int ci = 0; ci < 32; ++ci) {
            const float* wp = &rw2[(co * 32 + ci) * 3];
            const float* rp = &s_r1[ci * 32 + i];
            if (i > 0)  s += wp[0] * rp[-1];
            s += wp[1] * rp[0];
            if (i < 31) s += wp[2] * rp[1];
        }
        float gg = rbn2[co], bb = rbn2[32 + co], mm = rbn2[64 + co], vv = rbn2[96 + co];
        s = (s - mm) * (gg / sqrtf(vv + 1e-5f)) + bb;
        s_r2[idx] = fmaxf(s, 0.f);
    }
    __syncthreads();

    // comb = [mag_pool(64), ph_pool(32), rf(32), az(48)], nan_to_num'd
    if (t < 64) {
        s_comb[t] = n2n(g_poolm[b * 64 + t] * (1.f / 65536.f));
    } else if (t < 96) {
        s_comb[t] = n2n(g_poolp[b * 32 + (t - 64)] * (1.f / 65536.f));
    } else if (t < 128) {
        int co = t - 96;
        float s = 0.f;
        #pragma unroll
        for (int i = 0; i < 32; ++i) s += s_r2[co * 32 + i];
        s_comb[t] = n2n(s * (1.f / 32.f));
    } else if (t < 176) {
        s_comb[t] = n2n(g_az[b * 48 + (t - 128)]);
    }
    __syncthreads();

    // linear 176 -> 256
    float hv = lb1[t];
    for (int k = 0; k < 176; ++k) hv += lw1[t * 176 + k] * s_comb[k];
    s_red[t] = hv;
    __syncthreads();
    #pragma unroll
    for (int o = 128; o; o >>= 1) { if (t < o) s_red[t] += s_red[t + o]; __syncthreads(); }
    float mu = s_red[0] * (1.f / 256.f);
    __syncthreads();
    float d = hv - mu;
    s_red[t] = d * d;
    __syncthreads();
    #pragma unroll
    for (int o = 128; o; o >>= 1) { if (t < o) s_red[t] += s_red[t + o]; __syncthreads(); }
    float var = s_red[0] * (1.f / 256.f);
    __syncthreads();

    float hn = d / sqrtf(var + 1e-5f) * lng[t] + lnb[t];
    s_h[t] = fmaxf(hn, 0.f);
    __syncthreads();

    // linear 256 -> 128, clip, nan_to_num
    if (t < 128) {
        float o = lb2[t];
        for (int j = 0; j < 256; ++j) o += lw2[t * 256 + j] * s_h[j];
        if (isnan(o)) o = 0.f;
        else o = fminf(fmaxf(o, -100.f), 100.f);
        out[b * 128 + t] = o;
    }
}

// --------------------------------- launch ----------------------------------
extern "C" void kernel_launch(void* const* d_in, const int* in_sizes, int n_in,
                              void* d_out, int out_size)
{
    const float* x    = (const float*)d_in[0];
    const float* mw1  = (const float*)d_in[1];
    const float* mb1  = (const float*)d_in[2];
    const float* mbn1 = (const float*)d_in[3];
    const float* mw2  = (const float*)d_in[4];
    const float* mb2  = (const float*)d_in[5];
    const float* mbn2 = (const float*)d_in[6];
    const float* pw1  = (const float*)d_in[7];
    const float* pb1  = (const float*)d_in[8];
    const float* pbn1 = (const float*)d_in[9];
    const float* pw2  = (const float*)d_in[10];
    const float* pb2  = (const float*)d_in[11];
    const float* pbn2 = (const float*)d_in[12];
    const float* rw1  = (const float*)d_in[13];
    const float* rb1  = (const float*)d_in[14];
    const float* rbn1 = (const float*)d_in[15];
    const float* rw2  = (const float*)d_in[16];
    const float* rb2  = (const float*)d_in[17];
    const float* rbn2 = (const float*)d_in[18];
    const float* lw1  = (const float*)d_in[19];
    const float* lb1  = (const float*)d_in[20];
    const float* lng  = (const float*)d_in[21];
    const float* lnb  = (const float*)d_in[22];
    const float* lw2  = (const float*)d_in[23];
    const float* lb2  = (const float*)d_in[24];

    float *p_magsp, *p_phsp, *p_featm, *p_featp, *p_poolm, *p_poolp;
    cudaGetSymbolAddress((void**)&p_magsp, g_magsp);
    cudaGetSymbolAddress((void**)&p_phsp,  g_phsp);
    cudaGetSymbolAddress((void**)&p_featm, g_featm);
    cudaGetSymbolAddress((void**)&p_featp, g_featp);
    cudaGetSymbolAddress((void**)&p_poolm, g_poolm);
    cudaGetSymbolAddress((void**)&p_poolp, g_poolp);

    init_tw_kernel<<<1, 128>>>();
    rowfft_kernel<<<B_ * C_ * H_, 128>>>(x);
    colfft_kernel<<<B_ * C_ * WF, 128>>>();
    stats_kernel<<<B_ * C_, 256>>>();
    resize_kernel<<<(B_ * C_ * H_ * W_ + 255) / 256, 256>>>();

    // conv1: store features (bn+relu fused)
    conv3x3_kernel<3, 16><<<dim3(8, 8, B_ * 4), 256>>>(p_magsp, mw1, mb1, mbn1, p_featm, nullptr, 64);
    conv3x3_kernel<3, 16><<<dim3(8, 8, B_ * 2), 256>>>(p_phsp,  pw1, pb1, pbn1, p_featp, nullptr, 32);
    // conv2: fused bn+relu+pool (no feature write)
    conv3x3_kernel<64, 16><<<dim3(8, 8, B_ * 4), 256>>>(p_featm, mw2, mb2, mbn2, nullptr, p_poolm, 64);
    conv3x3_kernel<32, 16><<<dim3(8, 8, B_ * 2), 256>>>(p_featp, pw2, pb2, pbn2, nullptr, p_poolp, 32);

    final_kernel<<<B_, 256>>>(rw1, rb1, rbn1, rw2, rb2, rbn2,
                              lw1, lb1, lng, lnb, lw2, lb2, (float*)d_out);
}

// round 9
// speedup vs baseline: 1.8497x; 1.8497x over previous
#include <cuda_runtime.h>
#include <cuda_bf16.h>
#include <math.h>

// ---------------------------------------------------------------------------
// SpectralAnalyzer: rfft2 -> mag/phase -> radial/azimuthal stats ->
// bilinear resize -> 2x (conv3x3+bn+relu) branches (pooled) ->
// conv1d branch -> MLP head with LayerNorm.
// Shapes: x [16,3,256,256] -> out [16,128] fp32.
//
// Numerics proven in R8 (rel_err 2.8e-6): XLA divide->mul-by-reciprocal on
// bin chains, libdevice atan2f/hypotf/log1pf, forced-_rn bin arithmetic.
// Conv layers now use packed fma.rn.f32x2 (bit-identical fp32 FMA lanes,
// same accumulation order) + double-buffered staging with register prefetch.
// ---------------------------------------------------------------------------

#define B_     16
#define C_     3
#define H_     256
#define W_     256
#define WF     129            // W/2+1
#define NPTS   (H_ * WF)      // 33024
#define NRAD   32
#define NAZ    8
#define PI_F   3.14159265358979323846f
#define TWOPI_F 6.28318530717958647692f

// packed fp32x2 FMA: d = a*b + d (lanewise)
#define FMA2(d, a, b) \
    asm("fma.rn.f32x2 %0, %1, %2, %0;" : "+l"(d) : "l"(a), "l"(b))

// ------------------------- scratch (device globals) ------------------------
__device__ float2 g_tw   [128];                        // e^{-2*pi*i*k/256}
__device__ float2 g_freq [B_ * C_ * H_ * WF];          // row-fft intermediate
__device__ float  g_mag  [B_ * C_ * H_ * WF];
__device__ float  g_phase[B_ * C_ * H_ * WF];
__device__ float  g_magsp[B_ * C_ * H_ * W_];
__device__ float  g_phsp [B_ * C_ * H_ * W_];
__device__ float  g_featm[(size_t)B_ * 64 * H_ * W_];  // 268 MB
__device__ float  g_featp[(size_t)B_ * 32 * H_ * W_];  // 134 MB
__device__ float  g_radial[B_ * C_ * NRAD];
__device__ float  g_az    [B_ * NAZ * 2 * C_];
__device__ float  g_poolm [B_ * 64];
__device__ float  g_poolp [B_ * 32];

__device__ __forceinline__ float n2n(float v) {
    if (isnan(v)) return 0.f;
    if (isinf(v)) return v > 0.f ? 1e4f : -1e4f;
    return v;
}

// --------------------- twiddle table (double-accurate) ---------------------
__global__ void init_tw_kernel() {
    int k = threadIdx.x;                       // 128 threads
    double ang = -6.283185307179586476925286766559 * (double)k / 256.0;
    double s, c;
    sincos(ang, &s, &c);
    g_tw[k] = make_float2((float)c, (float)s);
    if (k < 64) {
        #pragma unroll
        for (int b = 0; b < B_; ++b) g_poolm[b * 64 + k] = 0.f;
    }
    if (k < 32) {
        #pragma unroll
        for (int b = 0; b < B_; ++b) g_poolp[b * 32 + k] = 0.f;
    }
}

// ------------------------------ FFT (len 256) ------------------------------
__device__ __forceinline__ void fft256(float* re, float* im,
                                       const float2* stw, int t) {
    #pragma unroll
    for (int len = 2; len <= 256; len <<= 1) {
        int half = len >> 1;
        int grp  = t / half;
        int pos  = t - grp * half;
        int i0   = grp * len + pos;
        int i1   = i0 + half;
        float2 w = stw[pos * (256 / len)];
        float ar = re[i0], ai = im[i0];
        float br = re[i1], bi = im[i1];
        float tr = w.x * br - w.y * bi;
        float ti = w.x * bi + w.y * br;
        re[i0] = ar + tr;  im[i0] = ai + ti;
        re[i1] = ar - tr;  im[i1] = ai - ti;
        __syncthreads();
    }
}

__global__ void rowfft_kernel(const float* __restrict__ x) {
    int row = blockIdx.x;                       // 12288 total
    const float* px = x + (size_t)row * W_;
    __shared__ float sre[256], sim[256];
    __shared__ float2 stw[128];
    int t = threadIdx.x;
    stw[t] = g_tw[t];
    #pragma unroll
    for (int i = t; i < 256; i += 128) {
        float v = px[i];
        v = fminf(fmaxf(v, -10.f), 10.f);
        int r = (int)(__brev((unsigned)i) >> 24);
        sre[r] = v;  sim[r] = 0.f;
    }
    __syncthreads();
    fft256(sre, sim, stw, t);
    for (int i = t; i < WF; i += 128)
        g_freq[(size_t)row * WF + i] = make_float2(sre[i], sim[i]);
}

__global__ void colfft_kernel() {
    int col = blockIdx.x;                       // 6192 total
    int bc = col / WF, w = col - bc * WF;
    const float2* base = g_freq + (size_t)bc * H_ * WF + w;
    __shared__ float sre[256], sim[256];
    __shared__ float2 stw[128];
    int t = threadIdx.x;
    stw[t] = g_tw[t];
    #pragma unroll
    for (int h = t; h < 256; h += 128) {
        float2 v = base[(size_t)h * WF];
        int r = (int)(__brev((unsigned)h) >> 24);
        sre[r] = v.x;  sim[r] = v.y;
    }
    __syncthreads();
    fft256(sre, sim, stw, t);
    const float INVPI = __fdiv_rn(1.f, PI_F);   // XLA: divide->mul-reciprocal
    #pragma unroll
    for (int h = t; h < 256; h += 128) {
        float re_ = sre[h], im_ = sim[h];
        float m = hypotf(re_, im_);
        m = fminf(fmaxf(m, 1e-8f), 1e6f);
        float ang = atan2f(im_, re_);
        float ph = __fmul_rn(ang, INVPI);
        ph = fminf(fmaxf(ph, -1.f), 1.f);
        size_t idx = (size_t)bc * NPTS + (size_t)h * WF + w;
        g_mag[idx]   = m;
        g_phase[idx] = ph;
    }
}

// -------------------- radial / azimuthal statistics ------------------------
__global__ void stats_kernel() {
    int bc = blockIdx.x;                        // 48 blocks
    int t  = threadIdx.x;                       // 256 threads
    __shared__ float rs[NRAD], rc[NRAD], s1[NAZ], s2[NAZ], ac[NAZ];
    if (t < NRAD) { rs[t] = 0.f; rc[t] = 0.f; }
    if (t < NAZ)  { s1[t] = 0.f; s2[t] = 0.f; ac[t] = 0.f; }
    __syncthreads();

    const float rmax      = __fsqrt_rn(0.5f);
    const float denom     = __fadd_rn(rmax, 1e-8f);
    const float inv_denom = __fdiv_rn(1.f, denom);
    const float C8        = __fmul_rn(__fdiv_rn(1.f, TWOPI_F), 8.f);
    const float* magp = g_mag + (size_t)bc * NPTS;
    for (int n = t; n < NPTS; n += 256) {
        int i = n / WF;
        int j = n - i * WF;
        float fy = (float)(i < 128 ? i : i - 256) * (1.f / 256.f);
        float fx = (float)j * (1.f / 256.f);
        float r2s = __fadd_rn(__fmul_rn(fx, fx), __fmul_rn(fy, fy));
        float radius = __fsqrt_rn(r2s);
        float rv = __fmul_rn(__fmul_rn(radius, inv_denom), 31.0f);
        int rb = (int)rv;  rb = min(max(rb, 0), NRAD - 1);

        float fx2 = __fadd_rn(fx, 1e-8f);
        float ang = atan2f(fy, fx2);
        float av  = __fmul_rn(__fadd_rn(ang, PI_F), C8);
        int ab = (int)av;  ab = min(max(ab, 0), NAZ - 1);

        float m = magp[n];
        atomicAdd(&rs[rb], m);
        atomicAdd(&rc[rb], 1.f);
        atomicAdd(&s1[ab], m);
        atomicAdd(&s2[ab], __fmul_rn(m, m));
        atomicAdd(&ac[ab], 1.f);
    }
    __syncthreads();

    int b = bc / C_, c = bc - b * C_;
    if (t < NRAD) {
        float cnt = fmaxf(rc[t], 1.f);
        float v = __fmul_rn(rs[t], __fdiv_rn(1.f, cnt));
        g_radial[(b * C_ + c) * NRAD + t] = fminf(fmaxf(v, 0.f), 1e6f);
    }
    if (t < NAZ) {
        float cnt = ac[t];
        float mean = 0.f, sd = 0.f;
        if (cnt > 0.f) {
            mean = __fmul_rn(s1[t], __fdiv_rn(1.f, cnt));
            float num = __fsub_rn(s2[t], __fmul_rn(cnt, __fmul_rn(mean, mean)));
            float var = __fmul_rn(num, __fdiv_rn(1.f, fmaxf(cnt - 1.f, 1.f)));
            sd = __fsqrt_rn(fmaxf(var, 0.f));
        }
        g_az[b * (NAZ * 2 * C_) + t * (2 * C_) + c]      = n2n(mean);
        g_az[b * (NAZ * 2 * C_) + t * (2 * C_) + C_ + c] = n2n(sd);
    }
}

// ------------------------- bilinear resize 129 -> 256 ----------------------
__global__ void resize_kernel() {
    int idx = blockIdx.x * blockDim.x + threadIdx.x;
    if (idx >= B_ * C_ * H_ * W_) return;
    int xo = idx & 255;
    int y  = (idx >> 8) & 255;
    int bc = idx >> 16;

    float sx = ((float)xo + 0.5f) * (129.f / 256.f) - 0.5f;
    float fl = floorf(sx);
    int j0 = (int)fl;
    float f = sx - fl;
    int ja = max(j0, 0);
    int jb = min(j0 + 1, WF - 1);

    size_t rowbase = (size_t)bc * NPTS + (size_t)y * WF;
    float m0 = g_mag[rowbase + ja], m1 = g_mag[rowbase + jb];
    float l0 = fminf(fmaxf(log1pf(m0), -20.f), 20.f);
    float l1 = fminf(fmaxf(log1pf(m1), -20.f), 20.f);
    g_magsp[idx] = (1.f - f) * l0 + f * l1;

    float p0 = g_phase[rowbase + ja], p1 = g_phase[rowbase + jb];
    g_phsp[idx] = (1.f - f) * p0 + f * p1;
}

// ------------------- conv3x3 + bn + relu (fp32x2 packed) -------------------
// Tile 32x32 pixels, 256 threads, 2x2 pixels/thread. COPB output channels
// per block processed as COPB/2 packed channel-pairs via fma.rn.f32x2.
// Weights for a pair live adjacent in smem -> one LDS.64 per tap.
// Input staging is double-buffered with register prefetch so LDG latency
// overlaps the FMA chain. If outPool != null: fused bn+relu+spatial-sum.
template <int CIN, int COPB>
__global__ void __launch_bounds__(256, 2)
conv3x3_kernel(const float* __restrict__ in, const float* __restrict__ wt,
               const float* __restrict__ bias, const float* __restrict__ bn,
               float* __restrict__ outFeat, float* __restrict__ outPool,
               int Cout)
{
    constexpr int NP = COPB / 2;                // channel pairs
    const int groups = Cout / COPB;
    const int b   = blockIdx.z / groups;
    const int g   = blockIdx.z - b * groups;
    const int coB = g * COPB;
    const int x0  = blockIdx.x * 32, y0 = blockIdx.y * 32;
    const int tid = threadIdx.x;
    const int tx  = (tid & 15) * 2, ty = (tid >> 4) * 2;

    __shared__ float  s_in[2][34 * 34];
    __shared__ float2 s_w2[CIN * 9 * NP];       // [ci][tap][pair] -> (w_even, w_odd)
    __shared__ float  s_pool[COPB];

    // weight preload into paired layout
    for (int idx = tid; idx < COPB * CIN * 9; idx += 256) {
        int c = idx / (CIN * 9);
        int r = idx - c * (CIN * 9);            // ci*9 + k
        float w = wt[(size_t)(coB + c) * CIN * 9 + r];
        reinterpret_cast<float*>(&s_w2[r * NP + (c >> 1)])[c & 1] = w;
    }

    unsigned long long acc2[NP][4];
    #pragma unroll
    for (int cp = 0; cp < NP; ++cp)
        acc2[cp][0] = acc2[cp][1] = acc2[cp][2] = acc2[cp][3] = 0ull;

    // prefetch registers (1156 elems / 256 threads -> up to 5 per thread)
    float pf[5];
    {
        const float* plane = in + ((size_t)(b * CIN)) * (H_ * W_);
        #pragma unroll
        for (int u = 0; u < 5; ++u) {
            int idx = tid + u * 256;
            if (idx < 34 * 34) {
                int iy = idx / 34, ix = idx - iy * 34;
                int gy = y0 + iy - 1, gx = x0 + ix - 1;
                pf[u] = (gy >= 0 && gy < H_ && gx >= 0 && gx < W_)
                        ? plane[gy * W_ + gx] : 0.f;
            }
        }
        #pragma unroll
        for (int u = 0; u < 5; ++u) {
            int idx = tid + u * 256;
            if (idx < 34 * 34) s_in[0][idx] = pf[u];
        }
    }
    __syncthreads();    // buf0 ready; also covers weight preload

    for (int ci = 0; ci < CIN; ++ci) {
        int cur = ci & 1;

        // issue next channel's loads (latency hidden by FMA chain below)
        if (ci + 1 < CIN) {
            const float* plane = in + ((size_t)(b * CIN + ci + 1)) * (H_ * W_);
            #pragma unroll
            for (int u = 0; u < 5; ++u) {
                int idx = tid + u * 256;
                if (idx < 34 * 34) {
                    int iy = idx / 34, ix = idx - iy * 34;
                    int gy = y0 + iy - 1, gx = x0 + ix - 1;
                    pf[u] = (gy >= 0 && gy < H_ && gx >= 0 && gx < W_)
                            ? plane[gy * W_ + gx] : 0.f;
                }
            }
        }

        // load 4x4 pixel patch, pack each value as (v, v)
        unsigned long long vv[16];
        #pragma unroll
        for (int dy = 0; dy < 4; ++dy)
            #pragma unroll
            for (int dx = 0; dx < 4; ++dx) {
                float v = s_in[cur][(ty + dy) * 34 + tx + dx];
                asm("mov.b64 %0, {%1, %1};" : "=l"(vv[dy * 4 + dx]) : "f"(v));
            }

        const float2* wbase = &s_w2[ci * 9 * NP];
        #pragma unroll
        for (int cp = 0; cp < NP; ++cp) {
            #pragma unroll
            for (int k = 0; k < 9; ++k) {
                int dy = k / 3, dx = k - dy * 3;
                unsigned long long wp =
                    *reinterpret_cast<const unsigned long long*>(&wbase[k * NP + cp]);
                FMA2(acc2[cp][0], wp, vv[dy * 4 + dx]);
                FMA2(acc2[cp][1], wp, vv[dy * 4 + dx + 1]);
                FMA2(acc2[cp][2], wp, vv[(dy + 1) * 4 + dx]);
                FMA2(acc2[cp][3], wp, vv[(dy + 1) * 4 + dx + 1]);
            }
        }

        // commit prefetched channel into the other buffer
        if (ci + 1 < CIN) {
            #pragma unroll
            for (int u = 0; u < 5; ++u) {
                int idx = tid + u * 256;
                if (idx < 34 * 34) s_in[cur ^ 1][idx] = pf[u];
            }
        }
        __syncthreads();
    }

    if (outPool) {
        if (tid < COPB) s_pool[tid] = 0.f;
        __syncthreads();
    }

    #pragma unroll
    for (int cp = 0; cp < NP; ++cp) {
        #pragma unroll
        for (int l = 0; l < 2; ++l) {
            int c  = 2 * cp + l;
            int co = coB + c;
            float gg = bn[co], bb = bn[Cout + co];
            float mm = bn[2 * Cout + co], vv_ = bn[3 * Cout + co];
            float sc = gg / sqrtf(vv_ + 1e-5f);
            float bi = bias[co];
            float lsum = 0.f;
            #pragma unroll
            for (int p = 0; p < 4; ++p) {
                float lo, hi;
                asm("mov.b64 {%0, %1}, %2;" : "=f"(lo), "=f"(hi) : "l"(acc2[cp][p]));
                float a = l ? hi : lo;
                float yv = (a + bi - mm) * sc + bb;
                yv = fmaxf(yv, 0.f);
                if (outFeat) {
                    int py = ty + (p >> 1), px = tx + (p & 1);
                    outFeat[(((size_t)(b * Cout + co)) * H_ + (y0 + py)) * W_ + (x0 + px)] = yv;
                } else {
                    lsum += yv;
                }
            }
            if (outPool) {
                #pragma unroll
                for (int o = 16; o; o >>= 1)
                    lsum += __shfl_down_sync(0xffffffffu, lsum, o);
                if ((tid & 31) == 0) atomicAdd(&s_pool[c], lsum);
            }
        }
    }
    if (outPool) {
        __syncthreads();
        if (tid < COPB) atomicAdd(&outPool[b * Cout + coB + tid], s_pool[tid]);
    }
}

// -------------- conv1d branch + concat + MLP head + LayerNorm --------------
__global__ void final_kernel(const float* __restrict__ rw1, const float* __restrict__ rb1,
                             const float* __restrict__ rbn1, const float* __restrict__ rw2,
                             const float* __restrict__ rb2, const float* __restrict__ rbn2,
                             const float* __restrict__ lw1, const float* __restrict__ lb1,
                             const float* __restrict__ lng, const float* __restrict__ lnb,
                             const float* __restrict__ lw2, const float* __restrict__ lb2,
                             float* __restrict__ out)
{
    int b = blockIdx.x, t = threadIdx.x;
    __shared__ float s_r0[96], s_r1[1024], s_r2[1024];
    __shared__ float s_comb[176], s_h[256], s_red[256];

    if (t < 96) s_r0[t] = g_radial[b * 96 + t];
    __syncthreads();

    for (int idx = t; idx < 1024; idx += 256) {
        int co = idx >> 5, i = idx & 31;
        float s = rb1[co];
        #pragma unroll
        for (int ci = 0; ci < 3; ++ci) {
            const float* wp = &rw1[(co * 3 + ci) * 3];
            if (i > 0)  s += wp[0] * s_r0[ci * 32 + i - 1];
            s += wp[1] * s_r0[ci * 32 + i];
            if (i < 31) s += wp[2] * s_r0[ci * 32 + i + 1];
        }
        float gg = rbn1[co], bb = rbn1[32 + co], mm = rbn1[64 + co], vv = rbn1[96 + co];
        s = (s - mm) * (gg / sqrtf(vv + 1e-5f)) + bb;
        s_r1[idx] = fmaxf(s, 0.f);
    }
    __syncthreads();

    for (int idx = t; idx < 1024; idx += 256) {
        int co = idx >> 5, i = idx & 31;
        float s = rb2[co];
        for (int ci = 0; ci < 32; ++ci) {
            const float* wp = &rw2[(co * 32 + ci) * 3];
            const float* rp = &s_r1[ci * 32 + i];
            if (i > 0)  s += wp[0] * rp[-1];
            s += wp[1] * rp[0];
            if (i < 31) s += wp[2] * rp[1];
        }
        float gg = rbn2[co], bb = rbn2[32 + co], mm = rbn2[64 + co], vv = rbn2[96 + co];
        s = (s - mm) * (gg / sqrtf(vv + 1e-5f)) + bb;
        s_r2[idx] = fmaxf(s, 0.f);
    }
    __syncthreads();

    if (t < 64) {
        s_comb[t] = n2n(g_poolm[b * 64 + t] * (1.f / 65536.f));
    } else if (t < 96) {
        s_comb[t] = n2n(g_poolp[b * 32 + (t - 64)] * (1.f / 65536.f));
    } else if (t < 128) {
        int co = t - 96;
        float s = 0.f;
        #pragma unroll
        for (int i = 0; i < 32; ++i) s += s_r2[co * 32 + i];
        s_comb[t] = n2n(s * (1.f / 32.f));
    } else if (t < 176) {
        s_comb[t] = n2n(g_az[b * 48 + (t - 128)]);
    }
    __syncthreads();

    float hv = lb1[t];
    for (int k = 0; k < 176; ++k) hv += lw1[t * 176 + k] * s_comb[k];
    s_red[t] = hv;
    __syncthreads();
    #pragma unroll
    for (int o = 128; o; o >>= 1) { if (t < o) s_red[t] += s_red[t + o]; __syncthreads(); }
    float mu = s_red[0] * (1.f / 256.f);
    __syncthreads();
    float d = hv - mu;
    s_red[t] = d * d;
    __syncthreads();
    #pragma unroll
    for (int o = 128; o; o >>= 1) { if (t < o) s_red[t] += s_red[t + o]; __syncthreads(); }
    float var = s_red[0] * (1.f / 256.f);
    __syncthreads();

    float hn = d / sqrtf(var + 1e-5f) * lng[t] + lnb[t];
    s_h[t] = fmaxf(hn, 0.f);
    __syncthreads();

    if (t < 128) {
        float o = lb2[t];
        for (int j = 0; j < 256; ++j) o += lw2[t * 256 + j] * s_h[j];
        if (isnan(o)) o = 0.f;
        else o = fminf(fmaxf(o, -100.f), 100.f);
        out[b * 128 + t] = o;
    }
}

// --------------------------------- launch ----------------------------------
extern "C" void kernel_launch(void* const* d_in, const int* in_sizes, int n_in,
                              void* d_out, int out_size)
{
    const float* x    = (const float*)d_in[0];
    const float* mw1  = (const float*)d_in[1];
    const float* mb1  = (const float*)d_in[2];
    const float* mbn1 = (const float*)d_in[3];
    const float* mw2  = (const float*)d_in[4];
    const float* mb2  = (const float*)d_in[5];
    const float* mbn2 = (const float*)d_in[6];
    const float* pw1  = (const float*)d_in[7];
    const float* pb1  = (const float*)d_in[8];
    const float* pbn1 = (const float*)d_in[9];
    const float* pw2  = (const float*)d_in[10];
    const float* pb2  = (const float*)d_in[11];
    const float* pbn2 = (const float*)d_in[12];
    const float* rw1  = (const float*)d_in[13];
    const float* rb1  = (const float*)d_in[14];
    const float* rbn1 = (const float*)d_in[15];
    const float* rw2  = (const float*)d_in[16];
    const float* rb2  = (const float*)d_in[17];
    const float* rbn2 = (const float*)d_in[18];
    const float* lw1  = (const float*)d_in[19];
    const float* lb1  = (const float*)d_in[20];
    const float* lng  = (const float*)d_in[21];
    const float* lnb  = (const float*)d_in[22];
    const float* lw2  = (const float*)d_in[23];
    const float* lb2  = (const float*)d_in[24];

    float *p_magsp, *p_phsp, *p_featm, *p_featp, *p_poolm, *p_poolp;
    cudaGetSymbolAddress((void**)&p_magsp, g_magsp);
    cudaGetSymbolAddress((void**)&p_phsp,  g_phsp);
    cudaGetSymbolAddress((void**)&p_featm, g_featm);
    cudaGetSymbolAddress((void**)&p_featp, g_featp);
    cudaGetSymbolAddress((void**)&p_poolm, g_poolm);
    cudaGetSymbolAddress((void**)&p_poolp, g_poolp);

    init_tw_kernel<<<1, 128>>>();
    rowfft_kernel<<<B_ * C_ * H_, 128>>>(x);
    colfft_kernel<<<B_ * C_ * WF, 128>>>();
    stats_kernel<<<B_ * C_, 256>>>();
    resize_kernel<<<(B_ * C_ * H_ * W_ + 255) / 256, 256>>>();

    // conv1: store features (bn+relu fused)
    conv3x3_kernel<3, 16><<<dim3(8, 8, B_ * 4), 256>>>(p_magsp, mw1, mb1, mbn1, p_featm, nullptr, 64);
    conv3x3_kernel<3, 16><<<dim3(8, 8, B_ * 2), 256>>>(p_phsp,  pw1, pb1, pbn1, p_featp, nullptr, 32);
    // conv2: fused bn+relu+pool (no feature write)
    conv3x3_kernel<64, 16><<<dim3(8, 8, B_ * 4), 256>>>(p_featm, mw2, mb2, mbn2, nullptr, p_poolm, 64);
    conv3x3_kernel<32, 16><<<dim3(8, 8, B_ * 2), 256>>>(p_featp, pw2, pb2, pbn2, nullptr, p_poolp, 32);

    final_kernel<<<B_, 256>>>(rw1, rb1, rbn1, rw2, rb2, rbn2,
                              lw1, lb1, lng, lnb, lw2, lb2, (float*)d_out);
}